// round 15
// baseline (speedup 1.0000x reference)
#include <cuda_runtime.h>
#include <cuda_fp16.h>
#include <cstdint>
#include <math_constants.h>

#define D       256
#define NT      65536
#define NE      4096
#define WINDOW  4.5f

// ---- smem layout (bytes) ----
#define APITCH  272                       // 256 data + 16 pad (odd multiple of 16 -> conflict-free ldmatrix)
#define AH_OFF  0
#define BB_OFF  (128 * APITCH)            // 34816
#define BSTAGE  (128 * APITCH)            // 34816 (128 codes x full k=256 bytes)
#define RED_OFF BB_OFF                    // reduction arrays alias B stages
#define SMEM_TOTAL (BB_OFF + 2 * BSTAGE)  // 104448 (~102KB) -> 2 CTAs/SM

__device__ float         g_eNormHalf[NE];
__device__ int           g_idx[NT];
__device__ int           g_fullCount;
__device__ int           g_fullList[NT];
__device__ int           g_candList[NT * 24];
__device__ unsigned char g_candCnt[NT];
__device__ unsigned char g_e8[NE * D];

// ---------------- helpers ----------------
__device__ __forceinline__ uint32_t smem_u32(const void* p) {
    uint32_t a;
    asm("{ .reg .u64 t; cvta.to.shared.u64 t, %1; cvt.u32.u64 %0, t; }" : "=r"(a) : "l"(p));
    return a;
}
__device__ __forceinline__ void ldsm4(uint32_t (&r)[4], uint32_t a) {
    asm volatile("ldmatrix.sync.aligned.m8n8.x4.shared.b16 {%0,%1,%2,%3}, [%4];"
                 : "=r"(r[0]), "=r"(r[1]), "=r"(r[2]), "=r"(r[3]) : "r"(a));
}
// fp8 e4m3 MMA, fp32 accumulate, k=32 per instruction
__device__ __forceinline__ void mma16832f8(float (&c)[4], const uint32_t (&a)[4],
                                           uint32_t b0, uint32_t b1) {
    asm volatile("mma.sync.aligned.m16n8k32.row.col.f32.e4m3.e4m3.f32 "
                 "{%0,%1,%2,%3}, {%4,%5,%6,%7}, {%8,%9}, {%0,%1,%2,%3};"
                 : "+f"(c[0]), "+f"(c[1]), "+f"(c[2]), "+f"(c[3])
                 : "r"(a[0]), "r"(a[1]), "r"(a[2]), "r"(a[3]), "r"(b0), "r"(b1));
}
// pack 4 fp32 -> 4 e4m3 bytes (byte0 = v.x)
__device__ __forceinline__ uint32_t pack_e4m3x4(float4 v) {
    uint16_t lo, hi;
    asm("cvt.rn.satfinite.e4m3x2.f32 %0, %1, %2;" : "=h"(lo) : "f"(v.y), "f"(v.x));
    asm("cvt.rn.satfinite.e4m3x2.f32 %0, %1, %2;" : "=h"(hi) : "f"(v.w), "f"(v.z));
    return (uint32_t)lo | ((uint32_t)hi << 16);
}

// exact fp32 score in the VALIDATED order (matches reference argmin behavior)
__device__ __forceinline__ float exact_score(const float* __restrict__ zrow,
                                             const float* __restrict__ e, int n) {
    float acc = 0.f;
    const float4* er = (const float4*)(e + (size_t)n * D);
    const float4* zr = (const float4*)zrow;
    #pragma unroll 8
    for (int k4 = 0; k4 < D / 4; k4++) {
        float4 ee = er[k4], zz = zr[k4];
        acc = __fmaf_rn(zz.x, ee.x, acc);
        acc = __fmaf_rn(zz.y, ee.y, acc);
        acc = __fmaf_rn(zz.z, ee.z, acc);
        acc = __fmaf_rn(zz.w, ee.w, acc);
    }
    return g_eNormHalf[n] - acc;
}

// ---------------------------------------------------------------------------
// prep: 0.5*||e||^2 AND fp8 image of e in one pass; zero counter.
// one warp per codebook row; lane covers 8 consecutive dims.
// ---------------------------------------------------------------------------
__global__ void prep_kernel(const float* __restrict__ e) {
    int row  = blockIdx.x * 8 + (threadIdx.x >> 5);
    int lane = threadIdx.x & 31;
    if (blockIdx.x == 0 && threadIdx.x == 0) g_fullCount = 0;
    const float4* p = (const float4*)(e + (size_t)row * D);
    float4 v0 = p[2 * lane], v1 = p[2 * lane + 1];
    float s = v0.x*v0.x + v0.y*v0.y + v0.z*v0.z + v0.w*v0.w
            + v1.x*v1.x + v1.y*v1.y + v1.z*v1.z + v1.w*v1.w;
    uint2 b;
    b.x = pack_e4m3x4(v0);
    b.y = pack_e4m3x4(v1);
    *(uint2*)(g_e8 + (size_t)row * D + lane * 8) = b;
    #pragma unroll
    for (int o = 16; o; o >>= 1) s += __shfl_xor_sync(0xFFFFFFFFu, s, o);
    if (lane == 0) g_eNormHalf[row] = 0.5f * s;
}

// ---------------------------------------------------------------------------
// cp.async fill of one e code tile (128 codes x 256 bytes) into stage t%2
// ---------------------------------------------------------------------------
__device__ __forceinline__ void issue_tile(uint32_t sbase, int t, int tid) {
    const int n0 = t * 128;
    const uint32_t sb = sbase + BB_OFF + (uint32_t)(t & 1) * BSTAGE;
    #pragma unroll
    for (int j = 0; j < 8; j++) {
        int lin = tid + j * 256;            // 0..2047
        int row = lin >> 4;
        int off = (lin & 15) * 16;
        const char* g = (const char*)g_e8 + (size_t)(n0 + row) * D + off;
        uint32_t s = sb + (uint32_t)(row * APITCH) + off;
        asm volatile("cp.async.cg.shared.global [%0], [%1], 16;" :: "r"(s), "l"(g));
    }
}

// ---------------------------------------------------------------------------
// pass-1: fp8 MMA (fp32 accumulate) + per-slot best-4 candidate generation.
// 256 threads, warps 4(m) x 2(n) over 128x128 output tiles; 32 code tiles,
// full k=256 per tile, 2-stage cp.async pipeline.
// ---------------------------------------------------------------------------
__global__ __launch_bounds__(256, 2)
void argmin_mma(const float* __restrict__ z) {
    extern __shared__ unsigned char sm[];
    const uint32_t sbase = smem_u32(sm);

    const int tid  = threadIdx.x;
    const int lane = tid & 31, wid = tid >> 5;
    const int warp_m = wid & 3, warp_n = wid >> 2;
    const int gid = lane >> 2, tig = lane & 3;
    const int m0 = blockIdx.x * 128;

    // ---- z tile -> fp8 smem (row-major, padded) ----
    for (int u = tid; u < 2048; u += 256) {
        int row = u >> 4, g16 = u & 15;
        const float4* zp = (const float4*)(z + (size_t)(m0 + row) * D) + g16 * 4;
        uint4 b;
        b.x = pack_e4m3x4(zp[0]);
        b.y = pack_e4m3x4(zp[1]);
        b.z = pack_e4m3x4(zp[2]);
        b.w = pack_e4m3x4(zp[3]);
        *(uint4*)(sm + AH_OFF + row * APITCH + g16 * 16) = b;
    }

    // ldmatrix lane offset (row = lane&15, byte-halfgroup = lane>>4)
    const uint32_t laneOff = (uint32_t)((lane & 15) * APITCH) + (uint32_t)((lane >> 4) * 16);
    const uint32_t aLane = sbase + AH_OFF + (uint32_t)(warp_m * 32 * APITCH) + laneOff;
    const uint32_t bLane = (uint32_t)(warp_n * 64 * APITCH) + laneOff;

    float acc[2][8][4];
    #pragma unroll
    for (int mt = 0; mt < 2; mt++)
        #pragma unroll
        for (int nt = 0; nt < 8; nt++)
            #pragma unroll
            for (int q = 0; q < 4; q++) acc[mt][nt][q] = 0.f;

    float bS1[4], bS2[4], bS3[4], bS4[4];
    int   bI1[4], bI2[4], bI3[4];
    #pragma unroll
    for (int i = 0; i < 4; i++) {
        bS1[i] = CUDART_INF_F; bS2[i] = CUDART_INF_F;
        bS3[i] = CUDART_INF_F; bS4[i] = CUDART_INF_F;
        bI1[i] = 0; bI2[i] = 0; bI3[i] = 0;
    }

    issue_tile(sbase, 0, tid);
    asm volatile("cp.async.commit_group;" ::: "memory");

    for (int t = 0; t < 32; t++) {
        asm volatile("cp.async.wait_group 0;" ::: "memory");
        __syncthreads();   // tile t resident & visible; all warps past compute(t-1)

        if (t + 1 < 32) {
            issue_tile(sbase, t + 1, tid);
            asm volatile("cp.async.commit_group;" ::: "memory");
        }

        const uint32_t bSt = sbase + BB_OFF + (uint32_t)(t & 1) * BSTAGE + bLane;

        #pragma unroll
        for (int ks = 0; ks < 8; ks++) {
            uint32_t ah[2][4];
            #pragma unroll
            for (int mt = 0; mt < 2; mt++)
                ldsm4(ah[mt], aLane + (uint32_t)(mt * 16 * APITCH) + ks * 32);
            uint32_t bh[8][2];
            #pragma unroll
            for (int p = 0; p < 4; p++) {
                uint32_t tt[4];
                ldsm4(tt, bSt + (uint32_t)(p * 16 * APITCH) + ks * 32);
                bh[2*p][0]   = tt[0]; bh[2*p][1]   = tt[2];
                bh[2*p+1][0] = tt[1]; bh[2*p+1][1] = tt[3];
            }
            #pragma unroll
            for (int mt = 0; mt < 2; mt++)
                #pragma unroll
                for (int nt = 0; nt < 8; nt++)
                    mma16832f8(acc[mt][nt], ah[mt], bh[nt][0], bh[nt][1]);
        }

        // fold code tile into per-slot best-4, reset acc
        const int n0 = t * 128;
        #pragma unroll
        for (int nt = 0; nt < 8; nt++) {
            int nb = n0 + warp_n * 64 + nt * 8 + tig * 2;
            float2 en = *(const float2*)&g_eNormHalf[nb];
            #pragma unroll
            for (int mt = 0; mt < 2; mt++) {
                #pragma unroll
                for (int half = 0; half < 2; half++) {
                    int lr = mt * 2 + half;
                    #pragma unroll
                    for (int q = 0; q < 2; q++) {
                        float s = (q ? en.y : en.x) - acc[mt][nt][half * 2 + q];
                        int   n = nb + q;
                        if (s < bS1[lr]) {
                            bS4[lr] = bS3[lr]; bS3[lr] = bS2[lr]; bI3[lr] = bI2[lr];
                            bS2[lr] = bS1[lr]; bI2[lr] = bI1[lr];
                            bS1[lr] = s; bI1[lr] = n;
                        } else if (s < bS2[lr]) {
                            bS4[lr] = bS3[lr]; bS3[lr] = bS2[lr]; bI3[lr] = bI2[lr];
                            bS2[lr] = s; bI2[lr] = n;
                        } else if (s < bS3[lr]) {
                            bS4[lr] = bS3[lr]; bS3[lr] = s; bI3[lr] = n;
                        } else if (s < bS4[lr]) {
                            bS4[lr] = s;
                        }
                    }
                    acc[mt][nt][half * 2]     = 0.f;
                    acc[mt][nt][half * 2 + 1] = 0.f;
                }
            }
        }
    }
    __syncthreads();   // compute done; reduction aliases B stages

    float* rS1 = (float*)(sm + RED_OFF);
    int*   rI1 = (int*)  (sm + RED_OFF + 4096);
    float* rS2 = (float*)(sm + RED_OFF + 8192);
    int*   rI2 = (int*)  (sm + RED_OFF + 12288);
    float* rS3 = (float*)(sm + RED_OFF + 16384);
    int*   rI3 = (int*)  (sm + RED_OFF + 20480);
    float* rS4 = (float*)(sm + RED_OFF + 24576);
    const int slot = warp_n * 4 + tig;
    #pragma unroll
    for (int lr = 0; lr < 4; lr++) {
        int r = warp_m * 32 + (lr >> 1) * 16 + (lr & 1) * 8 + gid;
        rS1[r * 8 + slot] = bS1[lr];
        rI1[r * 8 + slot] = bI1[lr];
        rS2[r * 8 + slot] = bS2[lr];
        rI2[r * 8 + slot] = bI2[lr];
        rS3[r * 8 + slot] = bS3[lr];
        rI3[r * 8 + slot] = bI3[lr];
        rS4[r * 8 + slot] = bS4[lr];
    }
    __syncthreads();
    if (tid < 128) {
        const int m = m0 + tid;
        float gbs = CUDART_INF_F; int gbi = 0x7FFFFFFF;
        #pragma unroll
        for (int s = 0; s < 8; s++) {
            float v = rS1[tid * 8 + s]; int i = rI1[tid * 8 + s];
            if (v < gbs || (v == gbs && i < gbi)) { gbs = v; gbi = i; }
        }
        g_idx[m] = gbi;
        const float win = gbs + WINDOW;
        int cand[24]; int cc = 0; bool fallback = false;
        #pragma unroll
        for (int s = 0; s < 8; s++) {
            if (rS1[tid * 8 + s] <= win) cand[cc++] = rI1[tid * 8 + s];
            if (rS2[tid * 8 + s] <= win) cand[cc++] = rI2[tid * 8 + s];
            if (rS3[tid * 8 + s] <= win) cand[cc++] = rI3[tid * 8 + s];
            if (rS4[tid * 8 + s] <= win) fallback = true;
        }
        if (fallback) {
            g_candCnt[m] = 1;   // fixcand skips; fixfull decides
            int p = atomicAdd(&g_fullCount, 1);
            g_fullList[p] = m;
        } else {
            g_candCnt[m] = (unsigned char)cc;
            if (cc > 1)
                for (int j = 0; j < cc; j++) g_candList[(size_t)m * 24 + j] = cand[j];
        }
    }
}

// ---------------------------------------------------------------------------
// fixcand: one warp per token; exact fp32 scores for its candidates,
// packed (score, idx) warp-min, writes g_idx. No atomics.
// ---------------------------------------------------------------------------
__global__ void fixcand_kernel(const float* __restrict__ z, const float* __restrict__ e) {
    const int lane = threadIdx.x & 31;
    const int wg   = (blockIdx.x * blockDim.x + threadIdx.x) >> 5;
    const int nwg  = (gridDim.x * blockDim.x) >> 5;
    for (int m = wg; m < NT; m += nwg) {
        int cc = g_candCnt[m];
        if (cc < 2) continue;
        float s = CUDART_INF_F;
        int   n = 0x7FFFFFFF;
        if (lane < cc) {
            n = g_candList[(size_t)m * 24 + lane];
            s = exact_score(z + (size_t)m * D, e, n);
        }
        uint32_t fb = __float_as_uint(s);
        fb = (fb & 0x80000000u) ? ~fb : (fb | 0x80000000u);
        unsigned long long key = ((unsigned long long)fb << 32) | (uint32_t)n;
        #pragma unroll
        for (int o = 16; o; o >>= 1) {
            unsigned long long other = __shfl_xor_sync(0xFFFFFFFFu, key, o);
            if (other < key) key = other;
        }
        if (lane == 0) g_idx[m] = (int)(key & 0xFFFFFFFFu);
    }
}

// ---------------------------------------------------------------------------
// fallback: exact full-scan (rare)
// ---------------------------------------------------------------------------
__global__ void fixfull_kernel(const float* __restrict__ z, const float* __restrict__ e) {
    __shared__ __align__(16) float sz[D];
    __shared__ float rs[256];
    __shared__ int   ri[256];
    const int tid = threadIdx.x;
    const int cnt = g_fullCount;
    for (int li = blockIdx.x; li < cnt; li += gridDim.x) {
        int m = g_fullList[li];
        sz[tid] = z[(size_t)m * D + tid];
        __syncthreads();
        float bs = CUDART_INF_F;
        int   bi = 0x7FFFFFFF;
        for (int rep = 0; rep < NE / 256; rep++) {
            int n = rep * 256 + tid;
            float s = exact_score(sz, e, n);
            if (s < bs || (s == bs && n < bi)) { bs = s; bi = n; }
        }
        rs[tid] = bs; ri[tid] = bi;
        __syncthreads();
        if (tid == 0) {
            float b = rs[0]; int i = ri[0];
            for (int t = 1; t < 256; t++)
                if (rs[t] < b || (rs[t] == b && ri[t] < i)) { b = rs[t]; i = ri[t]; }
            g_idx[m] = i;
        }
        __syncthreads();
    }
}

// ---------------------------------------------------------------------------
// gather (runs last, uses final g_idx)
// ---------------------------------------------------------------------------
__global__ void gather_kernel(const float* __restrict__ e,
                              float* __restrict__ out, int write_idx_tail) {
    int t   = blockIdx.x * blockDim.x + threadIdx.x;
    int row = t >> 6;
    int c   = t & 63;
    int idx = g_idx[row];
    ((float4*)out)[t] = ((const float4*)(e + (size_t)idx * D))[c];
    if (write_idx_tail && c == 0) out[(size_t)NT * D + row] = (float)idx;
}

extern "C" void kernel_launch(void* const* d_in, const int* in_sizes, int n_in,
                              void* d_out, int out_size) {
    const float* z = (const float*)d_in[0];
    const float* e = (const float*)d_in[1];
    float* out = (float*)d_out;
    int write_idx_tail = (out_size >= NT * D + NT) ? 1 : 0;

    cudaFuncSetAttribute(argmin_mma, cudaFuncAttributeMaxDynamicSharedMemorySize, SMEM_TOTAL);

    prep_kernel<<<NE / 8, 256>>>(e);
    argmin_mma<<<NT / 128, 256, SMEM_TOTAL>>>(z);
    fixcand_kernel<<<296, 256>>>(z, e);
    fixfull_kernel<<<64, 256>>>(z, e);
    gather_kernel<<<(NT * (D / 4)) / 256, 256>>>(e, out, write_idx_tail);
}